// round 5
// baseline (speedup 1.0000x reference)
#include <cuda_runtime.h>
#include <cuda_bf16.h>
#include <cstdint>
#include <math.h>

#define BATCH 8
#define SEQ   4096
#define DIM   64
#define TQ    128
#define TK    64
#define NTILE (SEQ / TK)

#define SMB    144                // smem row stride bytes (72 bf16): conflict-free ldmatrix
#define SM_QHI 0                  // 128 x 144
#define SM_QLO (128 * SMB)
#define SM_K0  (256 * SMB)        // buf0: 64 rows hi + 64 rows lo
#define SM_K1  (384 * SMB)        // buf1
#define SM_QN  (512 * SMB)        // 128 floats
#define SM_KLOD (64 * SMB)        // lo offset within a K buffer
#define SMEM_BYTES (512 * SMB + 512)   // 74240 B -> 2 CTAs/SM

static __device__ __forceinline__ uint32_t smem_u32(const void* p) {
    uint32_t a;
    asm("{ .reg .u64 t; cvta.to.shared.u64 t, %1; cvt.u32.u64 %0, t; }" : "=r"(a) : "l"(p));
    return a;
}
static __device__ __forceinline__ void ldsm_x4(uint32_t (&r)[4], uint32_t a) {
    asm volatile("ldmatrix.sync.aligned.m8n8.x4.shared.b16 {%0,%1,%2,%3}, [%4];"
                 : "=r"(r[0]), "=r"(r[1]), "=r"(r[2]), "=r"(r[3]) : "r"(a));
}
static __device__ __forceinline__ void ldsm_x4_t(uint32_t (&r)[4], uint32_t a) {
    asm volatile("ldmatrix.sync.aligned.m8n8.x4.trans.shared.b16 {%0,%1,%2,%3}, [%4];"
                 : "=r"(r[0]), "=r"(r[1]), "=r"(r[2]), "=r"(r[3]) : "r"(a));
}
static __device__ __forceinline__ void mma_bf16(float (&d)[4], const uint32_t (&a)[4],
                                                uint32_t b0, uint32_t b1) {
    asm volatile("mma.sync.aligned.m16n8k16.row.col.f32.bf16.bf16.f32 "
                 "{%0,%1,%2,%3}, {%4,%5,%6,%7}, {%8,%9}, {%0,%1,%2,%3};"
                 : "+f"(d[0]), "+f"(d[1]), "+f"(d[2]), "+f"(d[3])
                 : "r"(a[0]), "r"(a[1]), "r"(a[2]), "r"(a[3]), "r"(b0), "r"(b1));
}

// exp(x) without MUFU: 2^(x*log2e) via rint split + deg-5 poly (rel err ~1e-6).
static __device__ __forceinline__ float fast_exp(float x) {
    float z = fmaxf(x * 1.44269504089f, -126.0f);
    float r = rintf(z);
    float f = z - r;
    float p = 1.33335581e-3f;
    p = fmaf(p, f, 9.61812910e-3f);
    p = fmaf(p, f, 5.55041087e-2f);
    p = fmaf(p, f, 2.40226507e-1f);
    p = fmaf(p, f, 6.93147181e-1f);
    p = fmaf(p, f, 1.0f);
    return __int_as_float(__float_as_int(p) + (((int)r) << 23));
}
static __device__ __forceinline__ uint32_t pack_hi(float a, float b) {
    __nv_bfloat162 h = __float22bfloat162_rn(make_float2(a, b));
    return *reinterpret_cast<uint32_t*>(&h);
}
static __device__ __forceinline__ uint32_t pack_lo(float a, float b, uint32_t hbits) {
    __nv_bfloat162 h = *reinterpret_cast<__nv_bfloat162*>(&hbits);
    float2 hf = __bfloat1622float2(h);
    __nv_bfloat162 l = __float22bfloat162_rn(make_float2(a - hf.x, b - hf.y));
    return *reinterpret_cast<uint32_t*>(&l);
}

__global__ __launch_bounds__(256, 2)
void attn_hmma_kernel(const float* __restrict__ X, float* __restrict__ Y) {
    extern __shared__ char smc[];
    const uint32_t smb = smem_u32(smc);
    float* qn = (float*)(smc + SM_QN);

    const int tid  = threadIdx.x;
    const int wid  = tid >> 5;
    const int lane = tid & 31;
    const int q2   = lane >> 3;
    const int rr   = lane & 7;
    const int g    = lane >> 2;
    const int sg   = lane & 3;

    const int b  = blockIdx.y;
    const int q0 = blockIdx.x * TQ;
    const float* Xb = X + (size_t)b * SEQ * DIM;

    // staging slice for this thread: 4 float4 chunks of the 64x64 K tile
    const int st_r[4]  = { (tid + 0) >> 4, (tid + 256) >> 4, (tid + 512) >> 4, (tid + 768) >> 4 };
    const int st_c4    = tid & 15;

    // ---- Stage Q tile (128x64 fp32 -> bf16 hi/lo in smem) ----
    #pragma unroll
    for (int i = 0; i < 8; i++) {
        int e = tid + (i << 8);
        int r = e >> 4, c4 = e & 15;
        float4 v = *(const float4*)(Xb + (size_t)(q0 + r) * DIM + c4 * 4);
        uint32_t h0 = pack_hi(v.x, v.y), h1 = pack_hi(v.z, v.w);
        uint32_t l0 = pack_lo(v.x, v.y, h0), l1 = pack_lo(v.z, v.w, h1);
        *(uint2*)(smc + SM_QHI + r * SMB + c4 * 8) = make_uint2(h0, h1);
        *(uint2*)(smc + SM_QLO + r * SMB + c4 * 8) = make_uint2(l0, l1);
    }
    // ---- Stage K tile 0 into buf0 ----
    #pragma unroll
    for (int i = 0; i < 4; i++) {
        float4 v = *(const float4*)(Xb + (size_t)st_r[i] * DIM + st_c4 * 4);
        uint32_t h0 = pack_hi(v.x, v.y), h1 = pack_hi(v.z, v.w);
        uint32_t w0 = pack_lo(v.x, v.y, h0), w1 = pack_lo(v.z, v.w, h1);
        *(uint2*)(smc + SM_K0 + st_r[i] * SMB + st_c4 * 8) = make_uint2(h0, h1);
        *(uint2*)(smc + SM_K0 + SM_KLOD + st_r[i] * SMB + st_c4 * 8) = make_uint2(w0, w1);
    }
    // ---- Row norms (softmax shift m = ||q||^2) ----
    if (tid < TQ) {
        const float4* qp = (const float4*)(Xb + (size_t)(q0 + tid) * DIM);
        float s = 0.f;
        #pragma unroll
        for (int i = 0; i < 16; i++) {
            float4 v = qp[i];
            s += v.x * v.x + v.y * v.y + v.z * v.z + v.w * v.w;
        }
        qn[tid] = s;
    }
    __syncthreads();

    const float m0 = qn[wid * 16 + g];
    const float m1 = qn[wid * 16 + g + 8];

    // ---- ldmatrix lane address components ----
    const uint32_t qa_hi = smb + SM_QHI + (wid * 16 + (q2 & 1) * 8 + rr) * SMB + (q2 >> 1) * 16;
    const uint32_t qa_lo = qa_hi + (SM_QLO - SM_QHI);
    const uint32_t kb_off = ((q2 >> 1) * 8 + rr) * SMB + (q2 & 1) * 16;   // + buffer base
    const uint32_t vb_off = ((q2 & 1) * 8 + rr) * SMB + (q2 >> 1) * 16;   // + buffer base
    const uint32_t kbuf[2] = { smb + SM_K0, smb + SM_K1 };

    float O[8][4];
    #pragma unroll
    for (int i = 0; i < 8; i++)
        #pragma unroll
        for (int j = 0; j < 4; j++) O[i][j] = 0.f;
    float l0 = 0.f, l1 = 0.f;

    int cur = 0;
    for (int tile = 0; tile < NTILE; tile++) {
        const uint32_t kb_hi = kbuf[cur] + kb_off;
        const uint32_t kb_lo = kb_hi + SM_KLOD;
        const uint32_t vb_hi = kbuf[cur] + vb_off;
        const uint32_t vb_lo = vb_hi + SM_KLOD;

        // ---- S = Q K^T (3-chain bf16 split) ----
        float S[8][4];
        #pragma unroll
        for (int i = 0; i < 8; i++)
            #pragma unroll
            for (int j = 0; j < 4; j++) S[i][j] = 0.f;

        #pragma unroll
        for (int kc = 0; kc < 4; kc++) {
            uint32_t ah[4], al[4];
            ldsm_x4(ah, qa_hi + kc * 32);
            ldsm_x4(al, qa_lo + kc * 32);
            #pragma unroll
            for (int j = 0; j < 4; j++) {
                uint32_t bh[4], bl[4];
                ldsm_x4(bh, kb_hi + j * (16 * SMB) + kc * 32);
                ldsm_x4(bl, kb_lo + j * (16 * SMB) + kc * 32);
                mma_bf16(S[2*j],   ah, bh[0], bh[1]);
                mma_bf16(S[2*j+1], ah, bh[2], bh[3]);
                mma_bf16(S[2*j],   ah, bl[0], bl[1]);
                mma_bf16(S[2*j+1], ah, bl[2], bl[3]);
                mma_bf16(S[2*j],   al, bh[0], bh[1]);
                mma_bf16(S[2*j+1], al, bh[2], bh[3]);
            }
        }

        // ---- P = exp(S - m) -> bf16 hi/lo A-fragments ----
        uint32_t PH[8][2], PL[8][2];
        #pragma unroll
        for (int jb = 0; jb < 8; jb++) {
            float e0 = fast_exp(S[jb][0] - m0);
            float e1 = fast_exp(S[jb][1] - m0);
            float e2 = fast_exp(S[jb][2] - m1);
            float e3 = fast_exp(S[jb][3] - m1);
            l0 += e0 + e1;
            l1 += e2 + e3;
            PH[jb][0] = pack_hi(e0, e1); PL[jb][0] = pack_lo(e0, e1, PH[jb][0]);
            PH[jb][1] = pack_hi(e2, e3); PL[jb][1] = pack_lo(e2, e3, PH[jb][1]);
        }

        // ---- Prefetch next K tile (LDG latency hidden behind O-GEMM) ----
        float4 pf[4];
        const int nt = tile + 1;
        if (nt < NTILE) {
            const float* base = Xb + (size_t)nt * TK * DIM;
            #pragma unroll
            for (int i = 0; i < 4; i++)
                pf[i] = *(const float4*)(base + (size_t)st_r[i] * DIM + st_c4 * 4);
        }

        // ---- O += P V (V = K tile via ldmatrix.trans, 3-chain split) ----
        #pragma unroll
        for (int nc = 0; nc < 4; nc++) {
            uint32_t pah[4] = {PH[2*nc][0], PH[2*nc][1], PH[2*nc+1][0], PH[2*nc+1][1]};
            uint32_t pal[4] = {PL[2*nc][0], PL[2*nc][1], PL[2*nc+1][0], PL[2*nc+1][1]};
            #pragma unroll
            for (int cp = 0; cp < 4; cp++) {
                uint32_t bh[4], bl[4];
                ldsm_x4_t(bh, vb_hi + nc * (16 * SMB) + cp * 32);
                ldsm_x4_t(bl, vb_lo + nc * (16 * SMB) + cp * 32);
                mma_bf16(O[2*cp],   pah, bh[0], bh[1]);
                mma_bf16(O[2*cp+1], pah, bh[2], bh[3]);
                mma_bf16(O[2*cp],   pah, bl[0], bl[1]);
                mma_bf16(O[2*cp+1], pah, bl[2], bl[3]);
                mma_bf16(O[2*cp],   pal, bh[0], bh[1]);
                mma_bf16(O[2*cp+1], pal, bh[2], bh[3]);
            }
        }

        // ---- Convert + store next tile into alternate buffer ----
        if (nt < NTILE) {
            char* dst = smc + (cur ? SM_K0 : SM_K1);
            #pragma unroll
            for (int i = 0; i < 4; i++) {
                uint32_t h0 = pack_hi(pf[i].x, pf[i].y), h1 = pack_hi(pf[i].z, pf[i].w);
                uint32_t w0 = pack_lo(pf[i].x, pf[i].y, h0), w1 = pack_lo(pf[i].z, pf[i].w, h1);
                *(uint2*)(dst + st_r[i] * SMB + st_c4 * 8) = make_uint2(h0, h1);
                *(uint2*)(dst + SM_KLOD + st_r[i] * SMB + st_c4 * 8) = make_uint2(w0, w1);
            }
        }
        __syncthreads();
        cur ^= 1;
    }

    // ---- Epilogue ----
    l0 += __shfl_xor_sync(0xffffffffu, l0, 1);
    l0 += __shfl_xor_sync(0xffffffffu, l0, 2);
    l1 += __shfl_xor_sync(0xffffffffu, l1, 1);
    l1 += __shfl_xor_sync(0xffffffffu, l1, 2);
    const float inv0 = 1.f / l0;
    const float inv1 = 1.f / l1;

    const int row0 = q0 + wid * 16 + g;
    float* y0 = Y + ((size_t)b * SEQ + row0) * DIM + 2 * sg;
    float* y1 = y0 + 8 * DIM;
    #pragma unroll
    for (int jb = 0; jb < 8; jb++) {
        *(float2*)(y0 + jb * 8) = make_float2(O[jb][0] * inv0, O[jb][1] * inv0);
        *(float2*)(y1 + jb * 8) = make_float2(O[jb][2] * inv1, O[jb][3] * inv1);
    }
}

extern "C" void kernel_launch(void* const* d_in, const int* in_sizes, int n_in,
                              void* d_out, int out_size) {
    const float* X = (const float*)d_in[0];
    float* Y = (float*)d_out;

    cudaFuncSetAttribute(attn_hmma_kernel,
                         cudaFuncAttributeMaxDynamicSharedMemorySize, SMEM_BYTES);
    dim3 grid(SEQ / TQ, BATCH);
    attn_hmma_kernel<<<grid, 256, SMEM_BYTES>>>(X, Y);
}

// round 6
// speedup vs baseline: 1.1653x; 1.1653x over previous
#include <cuda_runtime.h>
#include <cuda_bf16.h>
#include <cstdint>
#include <math.h>

#define BATCH 8
#define SEQ   4096
#define DIM   64
#define TQ    128
#define TK    64
#define NTILE (SEQ / TK)

// K pipeline: 4 buffers x (hi 64x128B + lo 64x128B) = 64KB. Q staged over bufs 2,3.
#define BUFB  16384
#define SMEM_BYTES 65536

__device__ __align__(16) __nv_bfloat16 g_xhi[BATCH * SEQ * DIM];
__device__ __align__(16) __nv_bfloat16 g_xlo[BATCH * SEQ * DIM];
__device__ float g_qn[BATCH * SEQ];

static __device__ __forceinline__ uint32_t smem_u32(const void* p) {
    uint32_t a;
    asm("{ .reg .u64 t; cvta.to.shared.u64 t, %1; cvt.u32.u64 %0, t; }" : "=r"(a) : "l"(p));
    return a;
}
static __device__ __forceinline__ void cp16(uint32_t dst, const void* src) {
    asm volatile("cp.async.cg.shared.global [%0], [%1], 16;" :: "r"(dst), "l"(src) : "memory");
}
#define CP_COMMIT() asm volatile("cp.async.commit_group;" ::: "memory")
#define CP_WAIT(n)  asm volatile("cp.async.wait_group %0;" :: "n"(n) : "memory")

static __device__ __forceinline__ void ldsm_x4(uint32_t (&r)[4], uint32_t a) {
    asm volatile("ldmatrix.sync.aligned.m8n8.x4.shared.b16 {%0,%1,%2,%3}, [%4];"
                 : "=r"(r[0]), "=r"(r[1]), "=r"(r[2]), "=r"(r[3]) : "r"(a));
}
static __device__ __forceinline__ void ldsm_x4_t(uint32_t (&r)[4], uint32_t a) {
    asm volatile("ldmatrix.sync.aligned.m8n8.x4.trans.shared.b16 {%0,%1,%2,%3}, [%4];"
                 : "=r"(r[0]), "=r"(r[1]), "=r"(r[2]), "=r"(r[3]) : "r"(a));
}
static __device__ __forceinline__ void mma_bf16(float (&d)[4], const uint32_t (&a)[4],
                                                uint32_t b0, uint32_t b1) {
    asm volatile("mma.sync.aligned.m16n8k16.row.col.f32.bf16.bf16.f32 "
                 "{%0,%1,%2,%3}, {%4,%5,%6,%7}, {%8,%9}, {%0,%1,%2,%3};"
                 : "+f"(d[0]), "+f"(d[1]), "+f"(d[2]), "+f"(d[3])
                 : "r"(a[0]), "r"(a[1]), "r"(a[2]), "r"(a[3]), "r"(b0), "r"(b1));
}
static __device__ __forceinline__ float ex2f(float z) {
    float p;
    asm("ex2.approx.f32 %0, %1;" : "=f"(p) : "f"(z));
    return p;
}
static __device__ __forceinline__ uint32_t pack_hi(float a, float b) {
    __nv_bfloat162 h = __float22bfloat162_rn(make_float2(a, b));
    return *reinterpret_cast<uint32_t*>(&h);
}
static __device__ __forceinline__ uint32_t pack_lo(float a, float b, uint32_t hbits) {
    __nv_bfloat162 h = *reinterpret_cast<__nv_bfloat162*>(&hbits);
    float2 hf = __bfloat1622float2(h);
    __nv_bfloat162 l = __float22bfloat162_rn(make_float2(a - hf.x, b - hf.y));
    return *reinterpret_cast<uint32_t*>(&l);
}

// ---- Pre-pass 1: X (fp32) -> bf16 hi/lo split arrays ----
__global__ void prep_split_kernel(const float* __restrict__ X) {
    int i = blockIdx.x * 256 + threadIdx.x;   // float4 index
    float4 v = ((const float4*)X)[i];
    uint32_t h0 = pack_hi(v.x, v.y), h1 = pack_hi(v.z, v.w);
    uint32_t l0 = pack_lo(v.x, v.y, h0), l1 = pack_lo(v.z, v.w, h1);
    ((uint2*)g_xhi)[i] = make_uint2(h0, h1);
    ((uint2*)g_xlo)[i] = make_uint2(l0, l1);
}
// ---- Pre-pass 2: row norms (softmax shift m = ||x_row||^2) ----
__global__ void prep_norm_kernel(const float* __restrict__ X) {
    int t = blockIdx.x * 256 + threadIdx.x;
    int row = t >> 3, ln = t & 7;
    const float4* p = (const float4*)(X + (size_t)row * DIM) + ln * 2;
    float4 a = p[0], b = p[1];
    float s = a.x*a.x + a.y*a.y + a.z*a.z + a.w*a.w
            + b.x*b.x + b.y*b.y + b.z*b.z + b.w*b.w;
    s += __shfl_xor_sync(0xffffffffu, s, 1, 8);
    s += __shfl_xor_sync(0xffffffffu, s, 2, 8);
    s += __shfl_xor_sync(0xffffffffu, s, 4, 8);
    if (ln == 0) g_qn[row] = s;
}

// stage one K tile (hi+lo, 16KB) into buffer via cp.async; 4 chunks/thread
static __device__ __forceinline__ void stage_k(uint32_t buf, const __nv_bfloat16* xhi_b,
                                               const __nv_bfloat16* xlo_b, int kt, int tid) {
    #pragma unroll
    for (int k = 0; k < 2; k++) {
        int cid = tid + k * 256;
        int row = cid >> 3, c = cid & 7;
        uint32_t doff = (uint32_t)(row * 128 + ((c ^ (row & 7)) << 4));
        size_t soff = (size_t)(kt + row) * 128 + c * 16;
        cp16(buf + doff,        (const char*)xhi_b + soff);
        cp16(buf + 8192 + doff, (const char*)xlo_b + soff);
    }
}

__global__ __launch_bounds__(256, 2)
void attn_hmma_kernel(const float* __restrict__ X, float* __restrict__ Y) {
    extern __shared__ char smc[];
    const uint32_t smb = smem_u32(smc);

    const int tid  = threadIdx.x;
    const int wid  = tid >> 5;
    const int lane = tid & 31;
    const int q2   = lane >> 3;
    const int rr   = lane & 7;
    const int g    = lane >> 2;
    const int sg   = lane & 3;

    const int b  = blockIdx.y;
    const int q0 = blockIdx.x * TQ;
    const __nv_bfloat16* xhi_b = g_xhi + (size_t)b * SEQ * DIM;
    const __nv_bfloat16* xlo_b = g_xlo + (size_t)b * SEQ * DIM;

    const float m0 = g_qn[b * SEQ + q0 + wid * 16 + g];
    const float m1 = g_qn[b * SEQ + q0 + wid * 16 + g + 8];

    // ---- Stage Q tile (128 rows hi + lo = 32KB) into bufs 2..3 via cp.async ----
    const uint32_t qstage = smb + 2 * BUFB;
    #pragma unroll
    for (int k = 0; k < 4; k++) {
        int cid = tid + k * 256;                 // 1024 hi chunks
        int row = cid >> 3, c = cid & 7;
        uint32_t doff = (uint32_t)(row * 128 + ((c ^ (row & 7)) << 4));
        size_t soff = (size_t)(q0 + row) * 128 + c * 16;
        cp16(qstage + doff,         (const char*)xhi_b + soff);
        cp16(qstage + 16384 + doff, (const char*)xlo_b + soff);
    }
    CP_COMMIT();
    CP_WAIT(0);
    __syncthreads();

    // ---- Q fragments -> registers (A-frags for 4 k-chunks) ----
    uint32_t QH[4][4], QL[4][4];
    {
        int rowq = wid * 16 + (q2 & 1) * 8 + rr;
        uint32_t base = qstage + rowq * 128;
        #pragma unroll
        for (int kc = 0; kc < 4; kc++) {
            uint32_t ch = (uint32_t)((((q2 >> 1) + 2 * kc) ^ rr) << 4);
            ldsm_x4(QH[kc], base + ch);
            ldsm_x4(QL[kc], base + 16384 + ch);
        }
    }
    __syncthreads();   // Q reads done; bufs 2,3 reusable for K pipeline

    // ---- Preload K tiles 0..2 ----
    stage_k(smb + 0 * BUFB, xhi_b, xlo_b, 0 * TK, tid); CP_COMMIT();
    stage_k(smb + 1 * BUFB, xhi_b, xlo_b, 1 * TK, tid); CP_COMMIT();
    stage_k(smb + 2 * BUFB, xhi_b, xlo_b, 2 * TK, tid); CP_COMMIT();

    // ---- Per-lane in-buffer offsets (swizzle XOR value is rr for all patterns) ----
    const uint32_t kb_row = (uint32_t)(((q2 >> 1) * 8 + rr) * 128);
    const uint32_t vb_row = (uint32_t)(((q2 & 1) * 8 + rr) * 128);
    uint32_t kch[4], vch[4];
    #pragma unroll
    for (int i = 0; i < 4; i++) {
        kch[i] = (uint32_t)((((q2 & 1) + 2 * i) ^ rr) << 4);
        vch[i] = (uint32_t)((((q2 >> 1) + 2 * i) ^ rr) << 4);
    }

    float O[8][4];
    #pragma unroll
    for (int i = 0; i < 8; i++)
        #pragma unroll
        for (int j = 0; j < 4; j++) O[i][j] = 0.f;
    float l0 = 0.f, l1 = 0.f;

    for (int tile = 0; tile < NTILE; tile++) {
        CP_WAIT(2);          // tile's buffer landed
        __syncthreads();     // ...and prev tile's readers are done with buf (tile+3)&3

        if (tile + 3 < NTILE)
            stage_k(smb + ((tile + 3) & 3) * BUFB, xhi_b, xlo_b, (tile + 3) * TK, tid);
        CP_COMMIT();

        const uint32_t buf = smb + (tile & 3) * BUFB;

        // ---- S = Q K^T (3-chain bf16 split) ----
        float S[8][4];
        #pragma unroll
        for (int i = 0; i < 8; i++)
            #pragma unroll
            for (int j = 0; j < 4; j++) S[i][j] = 0.f;

        #pragma unroll
        for (int kc = 0; kc < 4; kc++) {
            #pragma unroll
            for (int j = 0; j < 4; j++) {
                uint32_t a = buf + kb_row + (uint32_t)(j * 2048) + kch[kc];
                uint32_t bh[4], bl[4];
                ldsm_x4(bh, a);
                ldsm_x4(bl, a + 8192);
                mma_bf16(S[2*j],   QH[kc], bh[0], bh[1]);
                mma_bf16(S[2*j+1], QH[kc], bh[2], bh[3]);
                mma_bf16(S[2*j],   QH[kc], bl[0], bl[1]);
                mma_bf16(S[2*j+1], QH[kc], bl[2], bl[3]);
                mma_bf16(S[2*j],   QL[kc], bh[0], bh[1]);
                mma_bf16(S[2*j+1], QL[kc], bh[2], bh[3]);
            }
        }

        // ---- P = exp(S - m) via MUFU ex2; pack bf16 hi/lo A-fragments ----
        uint32_t PH[8][2], PL[8][2];
        #pragma unroll
        for (int jb = 0; jb < 8; jb++) {
            float e0 = ex2f((S[jb][0] - m0) * 1.44269504f);
            float e1 = ex2f((S[jb][1] - m0) * 1.44269504f);
            float e2 = ex2f((S[jb][2] - m1) * 1.44269504f);
            float e3 = ex2f((S[jb][3] - m1) * 1.44269504f);
            l0 += e0 + e1;
            l1 += e2 + e3;
            PH[jb][0] = pack_hi(e0, e1); PL[jb][0] = pack_lo(e0, e1, PH[jb][0]);
            PH[jb][1] = pack_hi(e2, e3); PL[jb][1] = pack_lo(e2, e3, PH[jb][1]);
        }

        // ---- O += P V (V = same tile via ldmatrix.trans, 3-chain split) ----
        #pragma unroll
        for (int nc = 0; nc < 4; nc++) {
            uint32_t pah[4] = {PH[2*nc][0], PH[2*nc][1], PH[2*nc+1][0], PH[2*nc+1][1]};
            uint32_t pal[4] = {PL[2*nc][0], PL[2*nc][1], PL[2*nc+1][0], PL[2*nc+1][1]};
            #pragma unroll
            for (int cp = 0; cp < 4; cp++) {
                uint32_t a = buf + vb_row + (uint32_t)(nc * 2048) + vch[cp];
                uint32_t bh[4], bl[4];
                ldsm_x4_t(bh, a);
                ldsm_x4_t(bl, a + 8192);
                mma_bf16(O[2*cp],   pah, bh[0], bh[1]);
                mma_bf16(O[2*cp+1], pah, bh[2], bh[3]);
                mma_bf16(O[2*cp],   pah, bl[0], bl[1]);
                mma_bf16(O[2*cp+1], pah, bl[2], bl[3]);
                mma_bf16(O[2*cp],   pal, bh[0], bh[1]);
                mma_bf16(O[2*cp+1], pal, bh[2], bh[3]);
            }
        }
    }

    // ---- Epilogue ----
    l0 += __shfl_xor_sync(0xffffffffu, l0, 1);
    l0 += __shfl_xor_sync(0xffffffffu, l0, 2);
    l1 += __shfl_xor_sync(0xffffffffu, l1, 1);
    l1 += __shfl_xor_sync(0xffffffffu, l1, 2);
    const float inv0 = 1.f / l0;
    const float inv1 = 1.f / l1;

    const int row0 = q0 + wid * 16 + g;
    float* y0 = Y + ((size_t)b * SEQ + row0) * DIM + 2 * sg;
    float* y1 = y0 + 8 * DIM;
    #pragma unroll
    for (int jb = 0; jb < 8; jb++) {
        *(float2*)(y0 + jb * 8) = make_float2(O[jb][0] * inv0, O[jb][1] * inv0);
        *(float2*)(y1 + jb * 8) = make_float2(O[jb][2] * inv1, O[jb][3] * inv1);
    }
}

extern "C" void kernel_launch(void* const* d_in, const int* in_sizes, int n_in,
                              void* d_out, int out_size) {
    const float* X = (const float*)d_in[0];
    float* Y = (float*)d_out;

    prep_split_kernel<<<BATCH * SEQ * DIM / 4 / 256, 256>>>(X);
    prep_norm_kernel<<<BATCH * SEQ * 8 / 256, 256>>>(X);

    cudaFuncSetAttribute(attn_hmma_kernel,
                         cudaFuncAttributeMaxDynamicSharedMemorySize, SMEM_BYTES);
    dim3 grid(SEQ / TQ, BATCH);
    attn_hmma_kernel<<<grid, 256, SMEM_BYTES>>>(X, Y);
}

// round 7
// speedup vs baseline: 1.1748x; 1.0081x over previous
#include <cuda_runtime.h>
#include <cuda_bf16.h>
#include <cstdint>
#include <math.h>

#define BATCH 8
#define SEQ   4096
#define DIM   64
#define TQ    128
#define TK    64
#define NTILE (SEQ / TK)

// K pipeline: 4 buffers x (hi 64x128B + lo 64x128B) = 64KB. Q staged over bufs 2,3.
#define BUFB  16384
#define SMEM_BYTES 65536

__device__ __align__(16) __nv_bfloat16 g_xhi[BATCH * SEQ * DIM];
__device__ __align__(16) __nv_bfloat16 g_xlo[BATCH * SEQ * DIM];
__device__ float g_qn[BATCH * SEQ];

static __device__ __forceinline__ uint32_t smem_u32(const void* p) {
    uint32_t a;
    asm("{ .reg .u64 t; cvta.to.shared.u64 t, %1; cvt.u32.u64 %0, t; }" : "=r"(a) : "l"(p));
    return a;
}
static __device__ __forceinline__ void cp16(uint32_t dst, const void* src) {
    asm volatile("cp.async.cg.shared.global [%0], [%1], 16;" :: "r"(dst), "l"(src) : "memory");
}
#define CP_COMMIT() asm volatile("cp.async.commit_group;" ::: "memory")
#define CP_WAIT(n)  asm volatile("cp.async.wait_group %0;" :: "n"(n) : "memory")

static __device__ __forceinline__ void ldsm_x4(uint32_t (&r)[4], uint32_t a) {
    asm volatile("ldmatrix.sync.aligned.m8n8.x4.shared.b16 {%0,%1,%2,%3}, [%4];"
                 : "=r"(r[0]), "=r"(r[1]), "=r"(r[2]), "=r"(r[3]) : "r"(a));
}
static __device__ __forceinline__ void ldsm_x4_t(uint32_t (&r)[4], uint32_t a) {
    asm volatile("ldmatrix.sync.aligned.m8n8.x4.trans.shared.b16 {%0,%1,%2,%3}, [%4];"
                 : "=r"(r[0]), "=r"(r[1]), "=r"(r[2]), "=r"(r[3]) : "r"(a));
}
static __device__ __forceinline__ void mma_bf16(float (&d)[4], const uint32_t (&a)[4],
                                                uint32_t b0, uint32_t b1) {
    asm volatile("mma.sync.aligned.m16n8k16.row.col.f32.bf16.bf16.f32 "
                 "{%0,%1,%2,%3}, {%4,%5,%6,%7}, {%8,%9}, {%0,%1,%2,%3};"
                 : "+f"(d[0]), "+f"(d[1]), "+f"(d[2]), "+f"(d[3])
                 : "r"(a[0]), "r"(a[1]), "r"(a[2]), "r"(a[3]), "r"(b0), "r"(b1));
}
static __device__ __forceinline__ float ex2f(float z) {
    float p;
    asm("ex2.approx.f32 %0, %1;" : "=f"(p) : "f"(z));
    return p;
}
static __device__ __forceinline__ uint32_t pack_hi(float a, float b) {
    __nv_bfloat162 h = __float22bfloat162_rn(make_float2(a, b));
    return *reinterpret_cast<uint32_t*>(&h);
}
static __device__ __forceinline__ uint32_t pack_lo(float a, float b, uint32_t hbits) {
    __nv_bfloat162 h = *reinterpret_cast<__nv_bfloat162*>(&hbits);
    float2 hf = __bfloat1622float2(h);
    __nv_bfloat162 l = __float22bfloat162_rn(make_float2(a - hf.x, b - hf.y));
    return *reinterpret_cast<uint32_t*>(&l);
}

// ---- Pre-pass: X -> bf16 hi/lo arrays + row norms. 8 threads per row. ----
__global__ void prep_kernel(const float* __restrict__ X) {
    int t = blockIdx.x * 256 + threadIdx.x;
    int row = t >> 3, ln = t & 7;
    const float4* p = (const float4*)(X + (size_t)row * DIM) + ln * 2;
    float4 a = p[0], b = p[1];
    uint32_t h0 = pack_hi(a.x, a.y), h1 = pack_hi(a.z, a.w);
    uint32_t h2 = pack_hi(b.x, b.y), h3 = pack_hi(b.z, b.w);
    uint32_t l0 = pack_lo(a.x, a.y, h0), l1 = pack_lo(a.z, a.w, h1);
    uint32_t l2 = pack_lo(b.x, b.y, h2), l3 = pack_lo(b.z, b.w, h3);
    ((uint2*)g_xhi)[2*t]   = make_uint2(h0, h1);
    ((uint2*)g_xhi)[2*t+1] = make_uint2(h2, h3);
    ((uint2*)g_xlo)[2*t]   = make_uint2(l0, l1);
    ((uint2*)g_xlo)[2*t+1] = make_uint2(l2, l3);
    float s = a.x*a.x + a.y*a.y + a.z*a.z + a.w*a.w
            + b.x*b.x + b.y*b.y + b.z*b.z + b.w*b.w;
    s += __shfl_xor_sync(0xffffffffu, s, 1, 8);
    s += __shfl_xor_sync(0xffffffffu, s, 2, 8);
    s += __shfl_xor_sync(0xffffffffu, s, 4, 8);
    if (ln == 0) g_qn[row] = s;
}

// stage one K tile (hi+lo, 16KB) into buffer via cp.async
static __device__ __forceinline__ void stage_k(uint32_t buf, const __nv_bfloat16* xhi_b,
                                               const __nv_bfloat16* xlo_b, int kt, int tid) {
    #pragma unroll
    for (int k = 0; k < 2; k++) {
        int cid = tid + k * 256;
        int row = cid >> 3, c = cid & 7;
        uint32_t doff = (uint32_t)(row * 128 + ((c ^ (row & 7)) << 4));
        size_t soff = (size_t)(kt + row) * 128 + c * 16;
        cp16(buf + doff,        (const char*)xhi_b + soff);
        cp16(buf + 8192 + doff, (const char*)xlo_b + soff);
    }
}

__global__ __launch_bounds__(256, 2)
void attn_hmma_kernel(const float* __restrict__ X, float* __restrict__ Y) {
    extern __shared__ char smc[];
    const uint32_t smb = smem_u32(smc);

    const int tid  = threadIdx.x;
    const int wid  = tid >> 5;
    const int lane = tid & 31;
    const int q2   = lane >> 3;
    const int rr   = lane & 7;
    const int g    = lane >> 2;
    const int sg   = lane & 3;

    const int b  = blockIdx.y;
    const int q0 = blockIdx.x * TQ;
    const __nv_bfloat16* xhi_b = g_xhi + (size_t)b * SEQ * DIM;
    const __nv_bfloat16* xlo_b = g_xlo + (size_t)b * SEQ * DIM;

    const float m0 = g_qn[b * SEQ + q0 + wid * 16 + g];
    const float m1 = g_qn[b * SEQ + q0 + wid * 16 + g + 8];

    // ---- Stage Q tile (hi+lo = 32KB) into bufs 2..3 via cp.async ----
    const uint32_t qstage = smb + 2 * BUFB;
    #pragma unroll
    for (int k = 0; k < 4; k++) {
        int cid = tid + k * 256;
        int row = cid >> 3, c = cid & 7;
        uint32_t doff = (uint32_t)(row * 128 + ((c ^ (row & 7)) << 4));
        size_t soff = (size_t)(q0 + row) * 128 + c * 16;
        cp16(qstage + doff,         (const char*)xhi_b + soff);
        cp16(qstage + 16384 + doff, (const char*)xlo_b + soff);
    }
    CP_COMMIT();
    CP_WAIT(0);
    __syncthreads();

    // ---- Q fragments -> registers ----
    uint32_t QH[4][4], QL[4][4];
    {
        int rowq = wid * 16 + (q2 & 1) * 8 + rr;
        uint32_t base = qstage + rowq * 128;
        #pragma unroll
        for (int kc = 0; kc < 4; kc++) {
            uint32_t ch = (uint32_t)((((q2 >> 1) + 2 * kc) ^ rr) << 4);
            ldsm_x4(QH[kc], base + ch);
            ldsm_x4(QL[kc], base + 16384 + ch);
        }
    }
    __syncthreads();   // Q reads done; bufs 2,3 reusable for K pipeline

    stage_k(smb + 0 * BUFB, xhi_b, xlo_b, 0 * TK, tid); CP_COMMIT();
    stage_k(smb + 1 * BUFB, xhi_b, xlo_b, 1 * TK, tid); CP_COMMIT();
    stage_k(smb + 2 * BUFB, xhi_b, xlo_b, 2 * TK, tid); CP_COMMIT();

    const uint32_t kb_row = (uint32_t)(((q2 >> 1) * 8 + rr) * 128);
    const uint32_t vb_row = (uint32_t)(((q2 & 1) * 8 + rr) * 128);
    uint32_t kch[4], vch[4];
    #pragma unroll
    for (int i = 0; i < 4; i++) {
        kch[i] = (uint32_t)((((q2 & 1) + 2 * i) ^ rr) << 4);
        vch[i] = (uint32_t)((((q2 >> 1) + 2 * i) ^ rr) << 4);
    }

    float O[8][4];
    #pragma unroll
    for (int i = 0; i < 8; i++)
        #pragma unroll
        for (int j = 0; j < 4; j++) O[i][j] = 0.f;
    float l0 = 0.f, l1 = 0.f;

    for (int tile = 0; tile < NTILE; tile++) {
        CP_WAIT(2);
        __syncthreads();

        if (tile + 3 < NTILE)
            stage_k(smb + ((tile + 3) & 3) * BUFB, xhi_b, xlo_b, (tile + 3) * TK, tid);
        CP_COMMIT();

        const uint32_t buf = smb + (tile & 3) * BUFB;

        // ======== Half A: K rows 0..31 (n-blocks j=0,1) ========
        float SA[4][4];
        #pragma unroll
        for (int i = 0; i < 4; i++)
            #pragma unroll
            for (int j = 0; j < 4; j++) SA[i][j] = 0.f;
        #pragma unroll
        for (int kc = 0; kc < 4; kc++) {
            #pragma unroll
            for (int j = 0; j < 2; j++) {
                uint32_t a = buf + kb_row + (uint32_t)(j * 2048) + kch[kc];
                uint32_t bh[4], bl[4];
                ldsm_x4(bh, a);
                ldsm_x4(bl, a + 8192);
                mma_bf16(SA[2*j],   QH[kc], bh[0], bh[1]);
                mma_bf16(SA[2*j+1], QH[kc], bh[2], bh[3]);
                mma_bf16(SA[2*j],   QH[kc], bl[0], bl[1]);
                mma_bf16(SA[2*j+1], QH[kc], bl[2], bl[3]);
                mma_bf16(SA[2*j],   QL[kc], bh[0], bh[1]);
                mma_bf16(SA[2*j+1], QL[kc], bh[2], bh[3]);
            }
        }

        // ======== Half B: K rows 32..63 (n-blocks j=2,3) ========
        float SB[4][4];
        #pragma unroll
        for (int i = 0; i < 4; i++)
            #pragma unroll
            for (int j = 0; j < 4; j++) SB[i][j] = 0.f;
        #pragma unroll
        for (int kc = 0; kc < 4; kc++) {
            #pragma unroll
            for (int j = 2; j < 4; j++) {
                uint32_t a = buf + kb_row + (uint32_t)(j * 2048) + kch[kc];
                uint32_t bh[4], bl[4];
                ldsm_x4(bh, a);
                ldsm_x4(bl, a + 8192);
                mma_bf16(SB[2*(j-2)],   QH[kc], bh[0], bh[1]);
                mma_bf16(SB[2*(j-2)+1], QH[kc], bh[2], bh[3]);
                mma_bf16(SB[2*(j-2)],   QH[kc], bl[0], bl[1]);
                mma_bf16(SB[2*(j-2)+1], QH[kc], bl[2], bl[3]);
                mma_bf16(SB[2*(j-2)],   QL[kc], bh[0], bh[1]);
                mma_bf16(SB[2*(j-2)+1], QL[kc], bh[2], bh[3]);
            }
        }

        // ---- softmax A (interleaves under S_B MMA stream) ----
        uint32_t PHA[4][2], PLA[4][2];
        #pragma unroll
        for (int jb = 0; jb < 4; jb++) {
            float e0 = ex2f((SA[jb][0] - m0) * 1.44269504f);
            float e1 = ex2f((SA[jb][1] - m0) * 1.44269504f);
            float e2 = ex2f((SA[jb][2] - m1) * 1.44269504f);
            float e3 = ex2f((SA[jb][3] - m1) * 1.44269504f);
            l0 += e0 + e1;
            l1 += e2 + e3;
            PHA[jb][0] = pack_hi(e0, e1); PLA[jb][0] = pack_lo(e0, e1, PHA[jb][0]);
            PHA[jb][1] = pack_hi(e2, e3); PLA[jb][1] = pack_lo(e2, e3, PHA[jb][1]);
        }

        // ---- O += P_A * V rows 0..31 ----
        #pragma unroll
        for (int nc = 0; nc < 2; nc++) {
            uint32_t pah[4] = {PHA[2*nc][0], PHA[2*nc][1], PHA[2*nc+1][0], PHA[2*nc+1][1]};
            uint32_t pal[4] = {PLA[2*nc][0], PLA[2*nc][1], PLA[2*nc+1][0], PLA[2*nc+1][1]};
            #pragma unroll
            for (int cp = 0; cp < 4; cp++) {
                uint32_t a = buf + vb_row + (uint32_t)(nc * 2048) + vch[cp];
                uint32_t bh[4], bl[4];
                ldsm_x4_t(bh, a);
                ldsm_x4_t(bl, a + 8192);
                mma_bf16(O[2*cp],   pah, bh[0], bh[1]);
                mma_bf16(O[2*cp+1], pah, bh[2], bh[3]);
                mma_bf16(O[2*cp],   pah, bl[0], bl[1]);
                mma_bf16(O[2*cp+1], pah, bl[2], bl[3]);
                mma_bf16(O[2*cp],   pal, bh[0], bh[1]);
                mma_bf16(O[2*cp+1], pal, bh[2], bh[3]);
            }
        }

        // ---- softmax B (interleaves under O_A MMA stream) ----
        uint32_t PHB[4][2], PLB[4][2];
        #pragma unroll
        for (int jb = 0; jb < 4; jb++) {
            float e0 = ex2f((SB[jb][0] - m0) * 1.44269504f);
            float e1 = ex2f((SB[jb][1] - m0) * 1.44269504f);
            float e2 = ex2f((SB[jb][2] - m1) * 1.44269504f);
            float e3 = ex2f((SB[jb][3] - m1) * 1.44269504f);
            l0 += e0 + e1;
            l1 += e2 + e3;
            PHB[jb][0] = pack_hi(e0, e1); PLB[jb][0] = pack_lo(e0, e1, PHB[jb][0]);
            PHB[jb][1] = pack_hi(e2, e3); PLB[jb][1] = pack_lo(e2, e3, PHB[jb][1]);
        }

        // ---- O += P_B * V rows 32..63 ----
        #pragma unroll
        for (int nc = 2; nc < 4; nc++) {
            uint32_t pah[4] = {PHB[2*(nc-2)][0], PHB[2*(nc-2)][1], PHB[2*(nc-2)+1][0], PHB[2*(nc-2)+1][1]};
            uint32_t pal[4] = {PLB[2*(nc-2)][0], PLB[2*(nc-2)][1], PLB[2*(nc-2)+1][0], PLB[2*(nc-2)+1][1]};
            #pragma unroll
            for (int cp = 0; cp < 4; cp++) {
                uint32_t a = buf + vb_row + (uint32_t)(nc * 2048) + vch[cp];
                uint32_t bh[4], bl[4];
                ldsm_x4_t(bh, a);
                ldsm_x4_t(bl, a + 8192);
                mma_bf16(O[2*cp],   pah, bh[0], bh[1]);
                mma_bf16(O[2*cp+1], pah, bh[2], bh[3]);
                mma_bf16(O[2*cp],   pah, bl[0], bl[1]);
                mma_bf16(O[2*cp+1], pah, bl[2], bl[3]);
                mma_bf16(O[2*cp],   pal, bh[0], bh[1]);
                mma_bf16(O[2*cp+1], pal, bh[2], bh[3]);
            }
        }
    }

    // ---- Epilogue ----
    l0 += __shfl_xor_sync(0xffffffffu, l0, 1);
    l0 += __shfl_xor_sync(0xffffffffu, l0, 2);
    l1 += __shfl_xor_sync(0xffffffffu, l1, 1);
    l1 += __shfl_xor_sync(0xffffffffu, l1, 2);
    const float inv0 = 1.f / l0;
    const float inv1 = 1.f / l1;

    const int row0 = q0 + wid * 16 + g;
    float* y0 = Y + ((size_t)b * SEQ + row0) * DIM + 2 * sg;
    float* y1 = y0 + 8 * DIM;
    #pragma unroll
    for (int jb = 0; jb < 8; jb++) {
        *(float2*)(y0 + jb * 8) = make_float2(O[jb][0] * inv0, O[jb][1] * inv0);
        *(float2*)(y1 + jb * 8) = make_float2(O[jb][2] * inv1, O[jb][3] * inv1);
    }
}

extern "C" void kernel_launch(void* const* d_in, const int* in_sizes, int n_in,
                              void* d_out, int out_size) {
    const float* X = (const float*)d_in[0];
    float* Y = (float*)d_out;

    prep_kernel<<<BATCH * SEQ * 8 / 256, 256>>>(X);

    cudaFuncSetAttribute(attn_hmma_kernel,
                         cudaFuncAttributeMaxDynamicSharedMemorySize, SMEM_BYTES);
    dim3 grid(SEQ / TQ, BATCH);
    attn_hmma_kernel<<<grid, 256, SMEM_BYTES>>>(X, Y);
}